// round 6
// baseline (speedup 1.0000x reference)
#include <cuda_runtime.h>
#include <cuda_bf16.h>
#include <cstdint>

#define BB 4
#define CC 16
#define KK 16
#define HWHW (512 * 512)          // 262144
#define CHUNK 256                 // pixels per stage
#define NCHUNK (HWHW / CHUNK)     // 1024
#define GRIDX 74                  // 74*4 = 296 blocks = 2/SM, single wave
#define NTH 128
#define KPW 4                     // k's per warp (4 warps x 4 = 16)
#define NSTAGE 6

#define EMB_STAGE_FLOATS (CC * CHUNK)       // 4096 floats = 16 KB (emb only)
#define STAGE_BYTES (EMB_STAGE_FLOATS * 4)
#define SMEM_BYTES (NSTAGE * STAGE_BYTES)   // 96 KB

// stats per (b,k): [0..15] channel sums, [16] sum ||e||^2 over fg, [17] count
__device__ float g_stats[BB][KK][18];   // zeroed at load; re-zeroed by last block each launch
__device__ unsigned int g_done;

// ---------------- f32x2 helpers ----------------
__device__ __forceinline__ unsigned long long pack2(float lo, float hi) {
    unsigned long long r;
    asm("mov.b64 %0, {%1, %2};" : "=l"(r) : "f"(lo), "f"(hi));
    return r;
}
__device__ __forceinline__ void fma2(unsigned long long& acc, unsigned long long a, unsigned long long b) {
    asm("fma.rn.f32x2 %0, %1, %2, %3;" : "=l"(acc) : "l"(a), "l"(b), "l"(acc));
}
__device__ __forceinline__ void add2(unsigned long long& acc, unsigned long long a) {
    asm("add.rn.f32x2 %0, %1, %2;" : "=l"(acc) : "l"(acc), "l"(a));
}
__device__ __forceinline__ float unpack_sum(unsigned long long v) {
    float lo, hi;
    asm("mov.b64 {%0, %1}, %2;" : "=f"(lo), "=f"(hi) : "l"(v));
    return lo + hi;
}
__device__ __forceinline__ float warp_sum(float x) {
#pragma unroll
    for (int off = 16; off > 0; off >>= 1)
        x += __shfl_down_sync(0xffffffffu, x, off);
    return x;
}
__device__ __forceinline__ void cp_async16(uint32_t dst_smem, const void* src) {
    asm volatile("cp.async.cg.shared.global [%0], [%1], 16;" :: "r"(dst_smem), "l"(src) : "memory");
}

// ---------------- fused kernel ----------------
__global__ __launch_bounds__(NTH, 2)
void stats_kernel(const float* __restrict__ emb, const int* __restrict__ mask,
                  float* __restrict__ out) {
    extern __shared__ char smraw[];

    const int b   = blockIdx.y;
    const int bx  = blockIdx.x;
    const int tid = threadIdx.x;
    const int w   = tid >> 5;
    const int l   = tid & 31;

    const float* embB = emb + (size_t)b * CC * HWHW;
    // warp owns mask planes k = 4w .. 4w+3 (no cross-warp reuse -> direct LDG)
    const int4* mk[KPW];
#pragma unroll
    for (int kk = 0; kk < KPW; ++kk)
        mk[kk] = (const int4*)(mask + (size_t)b * KK * HWHW + (size_t)(KPW * w + kk) * HWHW);

    unsigned long long acc[KPW][CC];
    unsigned long long ssq[KPW], cnt[KPW];
#pragma unroll
    for (int kk = 0; kk < KPW; ++kk) {
#pragma unroll
        for (int c = 0; c < CC; ++c) acc[kk][c] = 0ull;
        ssq[kk] = 0ull; cnt[kk] = 0ull;
    }

    // emb-only prefetch: 1024 16B units per stage -> 8 per thread
    auto prefetch = [&](int stage, int ch) {
        if (ch < NCHUNK) {
            const int pix0 = ch * CHUNK;
            uint32_t se = (uint32_t)__cvta_generic_to_shared(smraw + stage * STAGE_BYTES);
#pragma unroll
            for (int j = 0; j < 8; ++j) {
                int u   = tid + j * NTH;        // 0..1023
                int c   = u >> 6;               // channel (64 16B units per channel)
                int off = (u & 63) << 2;        // float offset within row
                cp_async16(se + (uint32_t)(c * CHUNK + off) * 4,
                           embB + (size_t)c * HWHW + pix0 + off);
            }
        }
        asm volatile("cp.async.commit_group;" ::: "memory");
    };

#pragma unroll
    for (int s = 0; s < NSTAGE - 1; ++s)
        prefetch(s, bx + s * GRIDX);

    // mask register double-buffer: KPW x 2 subs int4 (each int4 = 4 pixels)
    int4 nm[KPW][2];
    {
        const int q = bx * (CHUNK / 4);
#pragma unroll
        for (int kk = 0; kk < KPW; ++kk) {
            nm[kk][0] = mk[kk][q + l];
            nm[kk][1] = mk[kk][q + l + 32];
        }
    }

    int cons = 0, pf = NSTAGE - 1;
    for (int ch = bx; ch < NCHUNK; ch += GRIDX) {
        int4 cm[KPW][2];
#pragma unroll
        for (int kk = 0; kk < KPW; ++kk) { cm[kk][0] = nm[kk][0]; cm[kk][1] = nm[kk][1]; }
        {
            int chn = ch + GRIDX;
            int chc = (chn < NCHUNK) ? chn : ch;   // clamp: values unused if loop ends
            const int q = chc * (CHUNK / 4);
#pragma unroll
            for (int kk = 0; kk < KPW; ++kk) {
                nm[kk][0] = mk[kk][q + l];
                nm[kk][1] = mk[kk][q + l + 32];
            }
        }

        asm volatile("cp.async.wait_group %0;" :: "n"(NSTAGE - 2) : "memory");
        __syncthreads();
        const float* eb = (const float*)(smraw + cons * STAGE_BYTES);

#pragma unroll
        for (int sub = 0; sub < 2; ++sub) {
            const int p4 = sub * 32 + l;    // ulonglong2 index (4 pixels)

            unsigned long long fx[KPW], fy[KPW];
#pragma unroll
            for (int kk = 0; kk < KPW; ++kk) {
                int4 m = cm[kk][sub];
                fx[kk] = pack2(m.x > 0 ? 1.0f : 0.0f, m.y > 0 ? 1.0f : 0.0f);
                fy[kk] = pack2(m.z > 0 ? 1.0f : 0.0f, m.w > 0 ? 1.0f : 0.0f);
            }

            unsigned long long s2A = 0ull, s2B = 0ull;
#pragma unroll
            for (int c = 0; c < CC; ++c) {
                ulonglong2 ev = ((const ulonglong2*)(eb + c * CHUNK))[p4];
                fma2(s2A, ev.x, ev.x);
                fma2(s2B, ev.y, ev.y);
#pragma unroll
                for (int kk = 0; kk < KPW; ++kk) {
                    fma2(acc[kk][c], ev.x, fx[kk]);
                    fma2(acc[kk][c], ev.y, fy[kk]);
                }
            }
#pragma unroll
            for (int kk = 0; kk < KPW; ++kk) {
                fma2(ssq[kk], s2A, fx[kk]);
                fma2(ssq[kk], s2B, fy[kk]);
                add2(cnt[kk], fx[kk]);
                add2(cnt[kk], fy[kk]);
            }
        }

        // prefetch overwrites the stage consumed (NSTAGE-1) iterations ago;
        // the next iteration's top-of-loop barrier orders readers vs this write
        prefetch(pf, ch + (NSTAGE - 1) * GRIDX);
        cons = (cons + 1 == NSTAGE) ? 0 : cons + 1;
        pf   = (pf   + 1 == NSTAGE) ? 0 : pf   + 1;
    }

    // ---- warp reduce + global accumulate ----
#pragma unroll
    for (int kk = 0; kk < KPW; ++kk) {
        const int k = w * KPW + kk;
#pragma unroll
        for (int c = 0; c < CC; ++c) {
            float v = warp_sum(unpack_sum(acc[kk][c]));
            if (l == 0) atomicAdd(&g_stats[b][k][c], v);
        }
        float s = warp_sum(unpack_sum(ssq[kk]));
        float n = warp_sum(unpack_sum(cnt[kk]));
        if (l == 0) {
            atomicAdd(&g_stats[b][k][16], s);
            atomicAdd(&g_stats[b][k][17], n);
        }
    }

    // ---- last-block epilogue: compute loss, write out, reset globals ----
    __shared__ bool is_last;
    __threadfence();
    if (tid == 0) {
        unsigned int v = atomicAdd(&g_done, 1u);
        is_last = (v == (unsigned int)(BB * GRIDX) - 1u);
    }
    __syncthreads();
    if (!is_last) return;
    __threadfence();

    float* sh_means = (float*)smraw;                      // [BB][KK][CC] = 1024
    float* sh_pull  = sh_means + BB * KK * CC;
    float* sh_valid = sh_pull + BB * KK;
    float* sh_push  = sh_valid + BB * KK;
    float* sh_pullb = sh_push + BB;
    float* sh_M     = sh_pullb + BB;

    const int t = tid;
    if (t < BB) sh_push[t] = 0.0f;

    if (t < BB * KK) {
        int bb = t >> 4, k = t & 15;
        volatile float* s = g_stats[bb][k];
        float cntv = s[17];
        float ssqv = s[16];
        bool valid = cntv > 0.0f;
        float inv = 1.0f / fmaxf(cntv, 1.0f);
        float dot = 0.0f;
#pragma unroll
        for (int c = 0; c < CC; ++c) {
            float sv = s[c];
            float m = sv * inv;
            sh_means[(bb * KK + k) * CC + c] = m;
            dot = fmaf(sv, m, dot);
        }
        sh_pull[bb * KK + k]  = valid ? (ssqv - dot) / (cntv + 1e-6f) : 0.0f;
        sh_valid[bb * KK + k] = valid ? 1.0f : 0.0f;
    }
    __syncthreads();

    for (int q = t; q < BB * KK * 18; q += NTH)
        ((float*)g_stats)[q] = 0.0f;
    if (t == 0) g_done = 0u;

    if (t < BB) {
        float M = 0.0f, ps = 0.0f;
        for (int k = 0; k < KK; ++k) { M += sh_valid[t * KK + k]; ps += sh_pull[t * KK + k]; }
        sh_M[t]     = M;
        sh_pullb[t] = ps / fmaxf(M, 1.0f);
    }

    float local[BB] = {0.0f, 0.0f, 0.0f, 0.0f};
    for (int idx = t; idx < BB * KK * KK; idx += NTH) {
        int bb = idx >> 8;
        int ij = idx & 255;
        int ii = ij >> 4, jj = ij & 15;
        if (ii < jj && sh_valid[bb * KK + ii] > 0.0f && sh_valid[bb * KK + jj] > 0.0f) {
            float d2 = 0.0f;
#pragma unroll
            for (int c = 0; c < CC; ++c) {
                float d = sh_means[(bb * KK + ii) * CC + c] - sh_means[(bb * KK + jj) * CC + c];
                d2 = fmaf(d, d, d2);
            }
            float dist = sqrtf(d2 + 1e-12f);
            float tm = fmaxf(1.5f - dist, 0.0f);
            local[bb] += tm * tm;
        }
    }
#pragma unroll
    for (int bb = 0; bb < BB; ++bb)
        if (local[bb] != 0.0f) atomicAdd(&sh_push[bb], local[bb]);
    __syncthreads();

    if (t == 0) {
        float loss = 0.0f;
        for (int bb = 0; bb < BB; ++bb) {
            float M = sh_M[bb];
            float npairs = M * (M - 1.0f) * 0.5f;
            float push = (M > 1.0f) ? sh_push[bb] / fmaxf(npairs, 1.0f) : 0.0f;
            loss += 0.5f * sh_pullb[bb] + push;   // DELTA_PULL = 0.5
        }
        out[0] = loss * (1.0f / BB);
    }
}

extern "C" void kernel_launch(void* const* d_in, const int* in_sizes, int n_in,
                              void* d_out, int out_size) {
    const float* emb  = (const float*)d_in[0];
    const int*   mask = (const int*)d_in[1];
    float* out = (float*)d_out;

    cudaFuncSetAttribute(stats_kernel, cudaFuncAttributeMaxDynamicSharedMemorySize, SMEM_BYTES);

    dim3 grid(GRIDX, BB);
    stats_kernel<<<grid, NTH, SMEM_BYTES>>>(emb, mask, out);
}

// round 7
// speedup vs baseline: 1.2977x; 1.2977x over previous
#include <cuda_runtime.h>
#include <cuda_bf16.h>
#include <cstdint>

#define BB 4
#define CC 16
#define KK 16
#define HWHW (512 * 512)          // 262144
#define CHUNK 128                 // pixels per stage
#define NCHUNK (HWHW / CHUNK)     // 2048
#define GRIDX 148                 // 148*4 = 592 blocks = 4/SM, single wave
#define NTH 128
#define KPW 4                     // k's per warp (4 warps x 4 = 16)
#define NSTAGE 3

#define EMB_STAGE_FLOATS (CC * CHUNK)       // 2048 floats = 8 KB
#define MSK_STAGE_INTS   (KK * CHUNK)       // 2048 ints   = 8 KB
#define STAGE_BYTES (EMB_STAGE_FLOATS * 4 + MSK_STAGE_INTS * 4)   // 16 KB
#define SMEM_BYTES (NSTAGE * STAGE_BYTES)   // 48 KB -> 4 blocks/SM

// stats per (b,k): [0..15] channel sums, [16] sum ||e||^2 over fg, [17] count
__device__ float g_stats[BB][KK][18];   // zeroed at load; re-zeroed by last block each launch
__device__ unsigned int g_done;

__device__ __forceinline__ float warp_sum(float x) {
#pragma unroll
    for (int off = 16; off > 0; off >>= 1)
        x += __shfl_down_sync(0xffffffffu, x, off);
    return x;
}
__device__ __forceinline__ void cp_async16(uint32_t dst_smem, const void* src) {
    asm volatile("cp.async.cg.shared.global [%0], [%1], 16;" :: "r"(dst_smem), "l"(src) : "memory");
}

// ---------------- fused kernel ----------------
__global__ __launch_bounds__(NTH, 4)
void stats_kernel(const float* __restrict__ emb, const int* __restrict__ mask,
                  float* __restrict__ out) {
    extern __shared__ char smraw[];

    const int b   = blockIdx.y;
    const int bx  = blockIdx.x;
    const int tid = threadIdx.x;
    const int w   = tid >> 5;
    const int l   = tid & 31;

    const float* embB = emb  + (size_t)b * CC * HWHW;
    const int*   mskB = mask + (size_t)b * KK * HWHW;

    // scalar f32 accumulators: 64 + 4 + 4 regs
    float acc[KPW][CC];
    float ssq[KPW], cnt[KPW];
#pragma unroll
    for (int kk = 0; kk < KPW; ++kk) {
#pragma unroll
        for (int c = 0; c < CC; ++c) acc[kk][c] = 0.0f;
        ssq[kk] = 0.0f; cnt[kk] = 0.0f;
    }

    // per stage: 512 emb units + 512 mask units of 16B -> 8 cp.async per thread
    auto prefetch = [&](int stage, int ch) {
        if (ch < NCHUNK) {
            const int pix0 = ch * CHUNK;
            uint32_t se = (uint32_t)__cvta_generic_to_shared(smraw + stage * STAGE_BYTES);
            uint32_t sk = se + EMB_STAGE_FLOATS * 4;
#pragma unroll
            for (int j = 0; j < 4; ++j) {
                int u   = tid + j * NTH;        // 0..511
                int c   = u >> 5;               // channel (32 16B units per channel)
                int off = (u & 31) << 2;        // float offset within row
                cp_async16(se + (uint32_t)(c * CHUNK + off) * 4,
                           embB + (size_t)c * HWHW + pix0 + off);
            }
#pragma unroll
            for (int j = 0; j < 4; ++j) {
                int u   = tid + j * NTH;
                int k   = u >> 5;
                int off = (u & 31) << 2;
                cp_async16(sk + (uint32_t)(k * CHUNK + off) * 4,
                           mskB + (size_t)k * HWHW + pix0 + off);
            }
        }
        asm volatile("cp.async.commit_group;" ::: "memory");
    };

    prefetch(0, bx);
    prefetch(1, bx + GRIDX);

    int cons = 0, pf = NSTAGE - 1;
    for (int ch = bx; ch < NCHUNK; ch += GRIDX) {
        asm volatile("cp.async.wait_group %0;" :: "n"(NSTAGE - 2) : "memory");
        __syncthreads();
        const float* eb = (const float*)(smraw + cons * STAGE_BYTES);
        const int*   mb = (const int*)(smraw + cons * STAGE_BYTES + EMB_STAGE_FLOATS * 4);

        // masks for this warp's 4 planes: one int4 per lane covers 4 pixels
        float mf[KPW][4];
#pragma unroll
        for (int kk = 0; kk < KPW; ++kk) {
            int4 m = ((const int4*)(mb + (w * KPW + kk) * CHUNK))[l];
            mf[kk][0] = m.x > 0 ? 1.0f : 0.0f;
            mf[kk][1] = m.y > 0 ? 1.0f : 0.0f;
            mf[kk][2] = m.z > 0 ? 1.0f : 0.0f;
            mf[kk][3] = m.w > 0 ? 1.0f : 0.0f;
        }

        float s2[4] = {0.0f, 0.0f, 0.0f, 0.0f};
#pragma unroll
        for (int c = 0; c < CC; ++c) {
            float4 e = ((const float4*)(eb + c * CHUNK))[l];
            s2[0] = fmaf(e.x, e.x, s2[0]);
            s2[1] = fmaf(e.y, e.y, s2[1]);
            s2[2] = fmaf(e.z, e.z, s2[2]);
            s2[3] = fmaf(e.w, e.w, s2[3]);
#pragma unroll
            for (int kk = 0; kk < KPW; ++kk) {
                float a = acc[kk][c];
                a = fmaf(e.x, mf[kk][0], a);
                a = fmaf(e.y, mf[kk][1], a);
                a = fmaf(e.z, mf[kk][2], a);
                a = fmaf(e.w, mf[kk][3], a);
                acc[kk][c] = a;
            }
        }
#pragma unroll
        for (int kk = 0; kk < KPW; ++kk) {
            float s = ssq[kk];
            s = fmaf(s2[0], mf[kk][0], s);
            s = fmaf(s2[1], mf[kk][1], s);
            s = fmaf(s2[2], mf[kk][2], s);
            s = fmaf(s2[3], mf[kk][3], s);
            ssq[kk] = s;
            cnt[kk] += (mf[kk][0] + mf[kk][1]) + (mf[kk][2] + mf[kk][3]);
        }

        // prefetch overwrites the stage consumed last iteration; the next
        // iteration's top-of-loop barrier orders readers vs this write
        prefetch(pf, ch + (NSTAGE - 1) * GRIDX);
        cons = (cons + 1 == NSTAGE) ? 0 : cons + 1;
        pf   = (pf   + 1 == NSTAGE) ? 0 : pf   + 1;
    }

    // ---- warp reduce + global accumulate ----
#pragma unroll
    for (int kk = 0; kk < KPW; ++kk) {
        const int k = w * KPW + kk;
#pragma unroll
        for (int c = 0; c < CC; ++c) {
            float v = warp_sum(acc[kk][c]);
            if (l == 0) atomicAdd(&g_stats[b][k][c], v);
        }
        float s = warp_sum(ssq[kk]);
        float n = warp_sum(cnt[kk]);
        if (l == 0) {
            atomicAdd(&g_stats[b][k][16], s);
            atomicAdd(&g_stats[b][k][17], n);
        }
    }

    // ---- last-block epilogue: compute loss, write out, reset globals ----
    __shared__ bool is_last;
    __threadfence();
    if (tid == 0) {
        unsigned int v = atomicAdd(&g_done, 1u);
        is_last = (v == (unsigned int)(BB * GRIDX) - 1u);
    }
    __syncthreads();
    if (!is_last) return;
    __threadfence();

    float* sh_means = (float*)smraw;                      // [BB][KK][CC] = 1024 floats
    float* sh_pull  = sh_means + BB * KK * CC;
    float* sh_valid = sh_pull + BB * KK;
    float* sh_push  = sh_valid + BB * KK;
    float* sh_pullb = sh_push + BB;
    float* sh_M     = sh_pullb + BB;

    const int t = tid;
    if (t < BB) sh_push[t] = 0.0f;

    if (t < BB * KK) {
        int bb = t >> 4, k = t & 15;
        volatile float* s = g_stats[bb][k];
        float cntv = s[17];
        float ssqv = s[16];
        bool valid = cntv > 0.0f;
        float inv = 1.0f / fmaxf(cntv, 1.0f);
        float dot = 0.0f;
#pragma unroll
        for (int c = 0; c < CC; ++c) {
            float sv = s[c];
            float m = sv * inv;
            sh_means[(bb * KK + k) * CC + c] = m;
            dot = fmaf(sv, m, dot);
        }
        sh_pull[bb * KK + k]  = valid ? (ssqv - dot) / (cntv + 1e-6f) : 0.0f;
        sh_valid[bb * KK + k] = valid ? 1.0f : 0.0f;
    }
    __syncthreads();

    for (int q = t; q < BB * KK * 18; q += NTH)
        ((float*)g_stats)[q] = 0.0f;
    if (t == 0) g_done = 0u;

    if (t < BB) {
        float M = 0.0f, ps = 0.0f;
        for (int k = 0; k < KK; ++k) { M += sh_valid[t * KK + k]; ps += sh_pull[t * KK + k]; }
        sh_M[t]     = M;
        sh_pullb[t] = ps / fmaxf(M, 1.0f);
    }

    float local[BB] = {0.0f, 0.0f, 0.0f, 0.0f};
    for (int idx = t; idx < BB * KK * KK; idx += NTH) {
        int bb = idx >> 8;
        int ij = idx & 255;
        int ii = ij >> 4, jj = ij & 15;
        if (ii < jj && sh_valid[bb * KK + ii] > 0.0f && sh_valid[bb * KK + jj] > 0.0f) {
            float d2 = 0.0f;
#pragma unroll
            for (int c = 0; c < CC; ++c) {
                float d = sh_means[(bb * KK + ii) * CC + c] - sh_means[(bb * KK + jj) * CC + c];
                d2 = fmaf(d, d, d2);
            }
            float dist = sqrtf(d2 + 1e-12f);
            float tm = fmaxf(1.5f - dist, 0.0f);
            local[bb] += tm * tm;
        }
    }
#pragma unroll
    for (int bb = 0; bb < BB; ++bb)
        if (local[bb] != 0.0f) atomicAdd(&sh_push[bb], local[bb]);
    __syncthreads();

    if (t == 0) {
        float loss = 0.0f;
        for (int bb = 0; bb < BB; ++bb) {
            float M = sh_M[bb];
            float npairs = M * (M - 1.0f) * 0.5f;
            float push = (M > 1.0f) ? sh_push[bb] / fmaxf(npairs, 1.0f) : 0.0f;
            loss += 0.5f * sh_pullb[bb] + push;   // DELTA_PULL = 0.5
        }
        out[0] = loss * (1.0f / BB);
    }
}

extern "C" void kernel_launch(void* const* d_in, const int* in_sizes, int n_in,
                              void* d_out, int out_size) {
    const float* emb  = (const float*)d_in[0];
    const int*   mask = (const int*)d_in[1];
    float* out = (float*)d_out;

    cudaFuncSetAttribute(stats_kernel, cudaFuncAttributeMaxDynamicSharedMemorySize, SMEM_BYTES);

    dim3 grid(GRIDX, BB);
    stats_kernel<<<grid, NTH, SMEM_BYTES>>>(emb, mask, out);
}